// round 1
// baseline (speedup 1.0000x reference)
#include <cuda_runtime.h>
#include <math.h>

// Problem constants (validated against in_sizes at launch)
#define D 96
#define ND_MAX (50000 * 96)

// Scratch (no cudaMalloc allowed)
__device__ float g_pooled[ND_MAX];
__device__ float g_h[ND_MAX];
__device__ float g_sum[D];
__device__ float g_sumsq[D];
__device__ float g_scale[D];
__device__ float g_shift[D];

// ---------------------------------------------------------------------------
// Kernel 1: pooled = (1 + eps) * feature ; zero BN accumulators
// ---------------------------------------------------------------------------
__global__ void init_kernel(const float* __restrict__ feature,
                            const float* __restrict__ eps, int ND) {
    int i = blockIdx.x * blockDim.x + threadIdx.x;
    float s = 1.0f + eps[0];
    if (i < ND) g_pooled[i] = s * feature[i];
    if (i < D) { g_sum[i] = 0.0f; g_sumsq[i] = 0.0f; }
}

// ---------------------------------------------------------------------------
// Kernel 2: scatter-add feature[src[e]] into pooled[dst[e]]
// One thread per (edge, float4-chunk): 24 chunks per edge (D=96).
// feature fits in L2 -> gather is L2-resident; atomics are L2-resident.
// ---------------------------------------------------------------------------
__global__ void scatter_kernel(const float* __restrict__ feature,
                               const int* __restrict__ src,
                               const int* __restrict__ dst, int E) {
    long long t = (long long)blockIdx.x * blockDim.x + threadIdx.x;
    int e = (int)(t / 24);
    int c = (int)(t % 24) * 4;
    if (e >= E) return;
    int s = src[e];
    int d = dst[e];
    float4 v = *reinterpret_cast<const float4*>(feature + (long long)s * D + c);
    float* p = g_pooled + (long long)d * D + c;
    atomicAdd(p + 0, v.x);
    atomicAdd(p + 1, v.y);
    atomicAdd(p + 2, v.z);
    atomicAdd(p + 3, v.w);
}

// ---------------------------------------------------------------------------
// Kernel 3: fused MLP  h = relu(pooled @ W1 + b1) @ W2 + b2
// Weights resident in shared memory (2 * 36 KB). One warp processes one node
// row at a time; lane L owns output columns L, L+32, L+64.
// Epilogue accumulates per-column sum / sumsq for BatchNorm, atomically
// reduced into g_sum / g_sumsq at the end.
// ---------------------------------------------------------------------------
__global__ void mlp_kernel(const float* __restrict__ W1,
                           const float* __restrict__ b1,
                           const float* __restrict__ W2,
                           const float* __restrict__ b2, int N) {
    extern __shared__ float sm[];
    float* W1s = sm;                  // 9216
    float* W2s = sm + 9216;           // 9216
    float* b1s = sm + 18432;          // 96
    float* b2s = sm + 18528;          // 96
    float* rows = sm + 18624;         // 8 warps * 96
    float* ts   = sm + 18624 + 768;   // 8 warps * 96

    int tid = threadIdx.x;
    for (int i = tid; i < D * D; i += blockDim.x) {
        W1s[i] = W1[i];
        W2s[i] = W2[i];
    }
    if (tid < D) { b1s[tid] = b1[tid]; b2s[tid] = b2[tid]; }
    __syncthreads();

    int w = tid >> 5, lane = tid & 31;
    float* rb = rows + w * D;
    float* tb = ts + w * D;
    int c0 = lane, c1 = lane + 32, c2 = lane + 64;

    float s0 = 0.f, s1 = 0.f, s2 = 0.f;
    float q0 = 0.f, q1 = 0.f, q2 = 0.f;

    for (int r = blockIdx.x * 8 + w; r < N; r += gridDim.x * 8) {
        const float* prow = g_pooled + (long long)r * D;
        rb[c0] = prow[c0];
        rb[c1] = prow[c1];
        rb[c2] = prow[c2];
        __syncwarp();

        // Layer 1: a[c] = b1[c] + sum_k rb[k] * W1[k,c]   (then ReLU)
        float a0 = b1s[c0], a1 = b1s[c1], a2 = b1s[c2];
        #pragma unroll
        for (int k = 0; k < D; k++) {
            float v = rb[k];                        // broadcast
            a0 = fmaf(v, W1s[k * D + c0], a0);      // conflict-free
            a1 = fmaf(v, W1s[k * D + c1], a1);
            a2 = fmaf(v, W1s[k * D + c2], a2);
        }
        a0 = fmaxf(a0, 0.f); a1 = fmaxf(a1, 0.f); a2 = fmaxf(a2, 0.f);
        tb[c0] = a0; tb[c1] = a1; tb[c2] = a2;
        __syncwarp();

        // Layer 2: h[c] = b2[c] + sum_k tb[k] * W2[k,c]
        float h0 = b2s[c0], h1 = b2s[c1], h2 = b2s[c2];
        #pragma unroll
        for (int k = 0; k < D; k++) {
            float v = tb[k];
            h0 = fmaf(v, W2s[k * D + c0], h0);
            h1 = fmaf(v, W2s[k * D + c1], h1);
            h2 = fmaf(v, W2s[k * D + c2], h2);
        }
        float* hrow = g_h + (long long)r * D;
        hrow[c0] = h0; hrow[c1] = h1; hrow[c2] = h2;

        s0 += h0; s1 += h1; s2 += h2;
        q0 += h0 * h0; q1 += h1 * h1; q2 += h2 * h2;
        __syncwarp();   // protect rb/tb before next iteration's writes
    }

    // Per-lane columns are distinct within a warp; contention only across warps.
    atomicAdd(&g_sum[c0], s0);  atomicAdd(&g_sum[c1], s1);  atomicAdd(&g_sum[c2], s2);
    atomicAdd(&g_sumsq[c0], q0); atomicAdd(&g_sumsq[c1], q1); atomicAdd(&g_sumsq[c2], q2);
}

// ---------------------------------------------------------------------------
// Kernel 4: BN statistics -> per-column affine (scale, shift)
// ---------------------------------------------------------------------------
__global__ void bn_stats_kernel(const float* __restrict__ gamma,
                                const float* __restrict__ beta, int N) {
    int c = threadIdx.x;
    if (c >= D) return;
    float invN = 1.0f / (float)N;
    float mean = g_sum[c] * invN;
    float var = g_sumsq[c] * invN - mean * mean;
    var = fmaxf(var, 0.0f);
    float sc = gamma[c] * rsqrtf(var + 1e-5f);
    g_scale[c] = sc;
    g_shift[c] = beta[c] - mean * sc;
}

// ---------------------------------------------------------------------------
// Kernel 5: out = relu(h * scale[c] + shift[c])
// ---------------------------------------------------------------------------
__global__ void bn_apply_kernel(float* __restrict__ out, int ND) {
    int i = blockIdx.x * blockDim.x + threadIdx.x;
    if (i >= ND) return;
    int c = i % D;
    out[i] = fmaxf(fmaf(g_h[i], g_scale[c], g_shift[c]), 0.0f);
}

// ---------------------------------------------------------------------------
extern "C" void kernel_launch(void* const* d_in, const int* in_sizes, int n_in,
                              void* d_out, int out_size) {
    const float* feature = (const float*)d_in[0];
    const int*   src     = (const int*)d_in[1];
    const int*   dst     = (const int*)d_in[2];
    const float* W1      = (const float*)d_in[3];
    const float* b1      = (const float*)d_in[4];
    const float* W2      = (const float*)d_in[5];
    const float* b2      = (const float*)d_in[6];
    const float* gamma   = (const float*)d_in[7];
    const float* beta    = (const float*)d_in[8];
    const float* eps     = (const float*)d_in[9];
    float* out = (float*)d_out;

    int ND = in_sizes[0];
    int E  = in_sizes[1];
    int N  = ND / D;

    // 1. pooled = (1+eps)*feature, zero BN accumulators
    {
        int threads = 256;
        int blocks = (ND + threads - 1) / threads;
        init_kernel<<<blocks, threads>>>(feature, eps, ND);
    }
    // 2. scatter-add
    {
        long long total = (long long)E * 24;
        int threads = 256;
        int blocks = (int)((total + threads - 1) / threads);
        scatter_kernel<<<blocks, threads>>>(feature, src, dst, E);
    }
    // 3. fused MLP + BN partial sums
    {
        static bool attr_set = false;
        size_t smem = (size_t)(9216 * 2 + 96 * 2 + 768 * 2) * sizeof(float); // 80640 B
        if (!attr_set) {
            cudaFuncSetAttribute(mlp_kernel,
                                 cudaFuncAttributeMaxDynamicSharedMemorySize,
                                 (int)smem);
            attr_set = true;
        }
        int blocks = 296;  // ~2 CTAs/SM, each warp loops over ~22 rows
        mlp_kernel<<<blocks, 256, smem>>>(W1, b1, W2, b2, N);
    }
    // 4. BN stats
    bn_stats_kernel<<<1, 128>>>(gamma, beta, N);
    // 5. BN apply + relu
    {
        int threads = 256;
        int blocks = (ND + threads - 1) / threads;
        bn_apply_kernel<<<blocks, threads>>>(out, ND);
    }
}

// round 16
// speedup vs baseline: 2.2398x; 2.2398x over previous
#include <cuda_runtime.h>
#include <math.h>

#define D 96
#define ND_MAX (50000 * 96)

// Scratch (no cudaMalloc allowed). 16B-aligned for float4 / red.v4 access.
__device__ __align__(16) float g_pooled[ND_MAX];
__device__ __align__(16) float g_h[ND_MAX];
__device__ float g_sum[D];
__device__ float g_sumsq[D];

// ---------------------------------------------------------------------------
// Kernel 1: pooled = (1 + eps) * feature (float4), zero BN accumulators
// ---------------------------------------------------------------------------
__global__ void init_kernel(const float* __restrict__ feature,
                            const float* __restrict__ eps, int ND4) {
    int i = blockIdx.x * blockDim.x + threadIdx.x;
    float s = 1.0f + eps[0];
    if (i < ND4) {
        float4 f = reinterpret_cast<const float4*>(feature)[i];
        f.x *= s; f.y *= s; f.z *= s; f.w *= s;
        reinterpret_cast<float4*>(g_pooled)[i] = f;
    }
    if (i < D) { g_sum[i] = 0.0f; g_sumsq[i] = 0.0f; }
}

// ---------------------------------------------------------------------------
// Kernel 2: scatter-add feature[src[e]] into pooled[dst[e]]
// One thread per (edge, float4 chunk) = 24 threads/edge.
// red.global.add.v4.f32 -> one LTS reduction op per 16 bytes (4x fewer ops
// than scalar atomicAdd). feature + pooled are L2-resident (38 MB total).
// ---------------------------------------------------------------------------
__global__ void scatter_kernel(const float* __restrict__ feature,
                               const int* __restrict__ src,
                               const int* __restrict__ dst, int E) {
    long long t = (long long)blockIdx.x * blockDim.x + threadIdx.x;
    int e = (int)(t / 24);
    int c = (int)(t % 24) * 4;
    if (e >= E) return;
    int s = src[e];
    int d = dst[e];
    float4 v = *reinterpret_cast<const float4*>(feature + (long long)s * D + c);
    float* p = g_pooled + (long long)d * D + c;
    asm volatile("red.global.add.v4.f32 [%0], {%1, %2, %3, %4};"
                 :: "l"(p), "f"(v.x), "f"(v.y), "f"(v.z), "f"(v.w)
                 : "memory");
}

// ---------------------------------------------------------------------------
// Kernel 3: fused MLP  h = relu(pooled @ W1 + b1) @ W2 + b2, with BN partial
// sums. 4-row blocking: each warp processes 4 node rows per iteration.
// Rows staged transposed in smem as float4 keyed by k, so the inner loop is
//   1 LDS.128 (broadcast, 4 row values) + 3 LDS.32 (W cols) -> 12 FFMA.
// Lane L owns output columns L, L+32, L+64 (conflict-free W reads).
// ---------------------------------------------------------------------------
#define MLP_WARPS 8
#define MLP_BLOCKS 296

__global__ void mlp_kernel(const float* __restrict__ W1,
                           const float* __restrict__ b1,
                           const float* __restrict__ W2,
                           const float* __restrict__ b2, int N) {
    extern __shared__ float sm[];
    float* W1s = sm;                       // 9216 floats
    float* W2s = sm + 9216;                // 9216
    float* b1s = sm + 18432;               // 96
    float* b2s = sm + 18528;               // 96
    float4* stage = (float4*)(sm + 18624); // MLP_WARPS * 96 float4

    int tid = threadIdx.x;
    for (int i = tid; i < D * D; i += blockDim.x) {
        W1s[i] = W1[i];
        W2s[i] = W2[i];
    }
    if (tid < D) { b1s[tid] = b1[tid]; b2s[tid] = b2[tid]; }
    __syncthreads();

    int w = tid >> 5, lane = tid & 31;
    float4* st = stage + w * D;
    int c0 = lane, c1 = lane + 32, c2 = lane + 64;

    float s0 = 0.f, s1 = 0.f, s2 = 0.f;
    float q0 = 0.f, q1 = 0.f, q2 = 0.f;

    // N = 50000 is divisible by 4, so every 4-row group is full.
    for (int r0 = (blockIdx.x * MLP_WARPS + w) * 4; r0 < N;
         r0 += gridDim.x * MLP_WARPS * 4) {
        const float* p = g_pooled + (long long)r0 * D;
        // Stage transposed: st[k] = {row0[k], row1[k], row2[k], row3[k]}
        st[c0] = make_float4(p[c0], p[D + c0], p[2 * D + c0], p[3 * D + c0]);
        st[c1] = make_float4(p[c1], p[D + c1], p[2 * D + c1], p[3 * D + c1]);
        st[c2] = make_float4(p[c2], p[D + c2], p[2 * D + c2], p[3 * D + c2]);
        __syncwarp();

        // Layer 1
        float A0[4], A1[4], A2[4];
        #pragma unroll
        for (int j = 0; j < 4; j++) { A0[j] = b1s[c0]; A1[j] = b1s[c1]; A2[j] = b1s[c2]; }
        #pragma unroll 8
        for (int k = 0; k < D; k++) {
            float4 v = st[k];
            float w0 = W1s[k * D + c0];
            float w1 = W1s[k * D + c1];
            float w2 = W1s[k * D + c2];
            A0[0] = fmaf(v.x, w0, A0[0]); A0[1] = fmaf(v.y, w0, A0[1]);
            A0[2] = fmaf(v.z, w0, A0[2]); A0[3] = fmaf(v.w, w0, A0[3]);
            A1[0] = fmaf(v.x, w1, A1[0]); A1[1] = fmaf(v.y, w1, A1[1]);
            A1[2] = fmaf(v.z, w1, A1[2]); A1[3] = fmaf(v.w, w1, A1[3]);
            A2[0] = fmaf(v.x, w2, A2[0]); A2[1] = fmaf(v.y, w2, A2[1]);
            A2[2] = fmaf(v.z, w2, A2[2]); A2[3] = fmaf(v.w, w2, A2[3]);
        }
        #pragma unroll
        for (int j = 0; j < 4; j++) {
            A0[j] = fmaxf(A0[j], 0.f); A1[j] = fmaxf(A1[j], 0.f); A2[j] = fmaxf(A2[j], 0.f);
        }
        __syncwarp();
        // Re-stage intermediate (reuse st): st[k] = relu(a)[rows 0..3]
        st[c0] = make_float4(A0[0], A0[1], A0[2], A0[3]);
        st[c1] = make_float4(A1[0], A1[1], A1[2], A1[3]);
        st[c2] = make_float4(A2[0], A2[1], A2[2], A2[3]);
        __syncwarp();

        // Layer 2
        float H0[4], H1[4], H2[4];
        #pragma unroll
        for (int j = 0; j < 4; j++) { H0[j] = b2s[c0]; H1[j] = b2s[c1]; H2[j] = b2s[c2]; }
        #pragma unroll 8
        for (int k = 0; k < D; k++) {
            float4 v = st[k];
            float w0 = W2s[k * D + c0];
            float w1 = W2s[k * D + c1];
            float w2 = W2s[k * D + c2];
            H0[0] = fmaf(v.x, w0, H0[0]); H0[1] = fmaf(v.y, w0, H0[1]);
            H0[2] = fmaf(v.z, w0, H0[2]); H0[3] = fmaf(v.w, w0, H0[3]);
            H1[0] = fmaf(v.x, w1, H1[0]); H1[1] = fmaf(v.y, w1, H1[1]);
            H1[2] = fmaf(v.z, w1, H1[2]); H1[3] = fmaf(v.w, w1, H1[3]);
            H2[0] = fmaf(v.x, w2, H2[0]); H2[1] = fmaf(v.y, w2, H2[1]);
            H2[2] = fmaf(v.z, w2, H2[2]); H2[3] = fmaf(v.w, w2, H2[3]);
        }

        float* hrow = g_h + (long long)r0 * D;
        #pragma unroll
        for (int j = 0; j < 4; j++) {
            hrow[j * D + c0] = H0[j];
            hrow[j * D + c1] = H1[j];
            hrow[j * D + c2] = H2[j];
            s0 += H0[j]; s1 += H1[j]; s2 += H2[j];
            q0 += H0[j] * H0[j]; q1 += H1[j] * H1[j]; q2 += H2[j] * H2[j];
        }
        __syncwarp();   // protect st before next iteration's writes
    }

    atomicAdd(&g_sum[c0], s0);   atomicAdd(&g_sum[c1], s1);   atomicAdd(&g_sum[c2], s2);
    atomicAdd(&g_sumsq[c0], q0); atomicAdd(&g_sumsq[c1], q1); atomicAdd(&g_sumsq[c2], q2);
}

// ---------------------------------------------------------------------------
// Kernel 4: fused BN finalize + apply + relu.
// Each block recomputes the 96 scale/shift values (trivial), then applies
// with float4 loads/stores. 96 floats/row = 24 float4s -> chunks never
// straddle a row, so column base = (i*4) % 96.
// ---------------------------------------------------------------------------
__global__ void bn_apply_kernel(const float* __restrict__ gamma,
                                const float* __restrict__ beta,
                                float* __restrict__ out, int N, int ND4) {
    __shared__ float sc[D], sh[D];
    int t = threadIdx.x;
    if (t < D) {
        float invN = 1.0f / (float)N;
        float mean = g_sum[t] * invN;
        float var = fmaxf(g_sumsq[t] * invN - mean * mean, 0.0f);
        float s = gamma[t] * rsqrtf(var + 1e-5f);
        sc[t] = s;
        sh[t] = beta[t] - mean * s;
    }
    __syncthreads();
    for (int i = blockIdx.x * blockDim.x + t; i < ND4; i += gridDim.x * blockDim.x) {
        float4 h = reinterpret_cast<const float4*>(g_h)[i];
        int cb = (i * 4) % D;
        float4 o;
        o.x = fmaxf(fmaf(h.x, sc[cb + 0], sh[cb + 0]), 0.0f);
        o.y = fmaxf(fmaf(h.y, sc[cb + 1], sh[cb + 1]), 0.0f);
        o.z = fmaxf(fmaf(h.z, sc[cb + 2], sh[cb + 2]), 0.0f);
        o.w = fmaxf(fmaf(h.w, sc[cb + 3], sh[cb + 3]), 0.0f);
        reinterpret_cast<float4*>(out)[i] = o;
    }
}

// ---------------------------------------------------------------------------
extern "C" void kernel_launch(void* const* d_in, const int* in_sizes, int n_in,
                              void* d_out, int out_size) {
    const float* feature = (const float*)d_in[0];
    const int*   src     = (const int*)d_in[1];
    const int*   dst     = (const int*)d_in[2];
    const float* W1      = (const float*)d_in[3];
    const float* b1      = (const float*)d_in[4];
    const float* W2      = (const float*)d_in[5];
    const float* b2      = (const float*)d_in[6];
    const float* gamma   = (const float*)d_in[7];
    const float* beta    = (const float*)d_in[8];
    const float* eps     = (const float*)d_in[9];
    float* out = (float*)d_out;

    int ND = in_sizes[0];
    int E  = in_sizes[1];
    int N  = ND / D;
    int ND4 = ND / 4;

    // 1. pooled = (1+eps)*feature, zero BN accumulators
    {
        int threads = 256;
        int blocks = (ND4 + threads - 1) / threads;
        init_kernel<<<blocks, threads>>>(feature, eps, ND4);
    }
    // 2. scatter-add (vector reductions)
    {
        long long total = (long long)E * 24;
        int threads = 256;
        int blocks = (int)((total + threads - 1) / threads);
        scatter_kernel<<<blocks, threads>>>(feature, src, dst, E);
    }
    // 3. fused MLP + BN partial sums
    {
        static bool attr_set = false;
        size_t smem = (size_t)(18624 + MLP_WARPS * D * 4) * sizeof(float); // 86784 B
        if (!attr_set) {
            cudaFuncSetAttribute(mlp_kernel,
                                 cudaFuncAttributeMaxDynamicSharedMemorySize,
                                 (int)smem);
            attr_set = true;
        }
        mlp_kernel<<<MLP_BLOCKS, MLP_WARPS * 32, smem>>>(W1, b1, W2, b2, N);
    }
    // 4. BN finalize + apply + relu
    {
        int threads = 256;
        int blocks = 592;
        bn_apply_kernel<<<blocks, threads>>>(gamma, beta, out, N, ND4);
    }
}